// round 1
// baseline (speedup 1.0000x reference)
#include <cuda_runtime.h>
#include <math.h>

#define NUM_CURVES 256
#define N_CTRL 10
#define NUM_GAUSS 16384   // 256 curves * 64 points
#define IMG 256
#define TILE 16
#define CUT 20.0f

// ---------------- device globals (scratch; no allocs allowed) ----------------
__device__ float2 g_mean[NUM_GAUSS];          // depth-sorted gaussian centers
__device__ float  sc_pA[NUM_CURVES];          // 0.5*conic0 (sorted by depth rank)
__device__ float  sc_pB[NUM_CURVES];          // conic1
__device__ float  sc_pC[NUM_CURVES];          // 0.5*conic2
__device__ float  sc_r [NUM_CURVES];
__device__ float  sc_g [NUM_CURVES];
__device__ float  sc_b [NUM_CURVES];
__device__ float  sc_al[NUM_CURVES];
__device__ float  sc_rad[NUM_CURVES];
__device__ int    d_ord[NUM_CURVES];          // rank -> original curve index

__device__ __forceinline__ float sigmoidf_(float x) {
    return 1.0f / (1.0f + __expf(-x));
}

// ---------------- kernel 1: per-curve params + stable depth sort -------------
__global__ void prep_curves(const float* __restrict__ chol,
                            const float* __restrict__ feat,
                            const float* __restrict__ opac,
                            const float* __restrict__ depth)
{
    int i = threadIdx.x;                       // 256 threads, 1 block
    __shared__ float sd[NUM_CURVES];
    sd[i] = depth[i];
    __syncthreads();

    float di = sd[i];
    int rank = 0;
    #pragma unroll 8
    for (int j = 0; j < NUM_CURVES; j++) {
        float dj = sd[j];
        rank += (dj < di) || (dj == di && j < i);   // stable argsort semantics
    }

    float c0 = chol[3*i + 0] + 0.5f;
    float c1 = chol[3*i + 1];
    float c2 = chol[3*i + 2] + 0.5f;
    float s00 = c0*c0;
    float s01 = c0*c1;
    float s11 = c1*c1 + c2*c2;
    float det = s00*s11 - s01*s01;
    float inv = 1.0f / det;
    float A  = s11 * inv;    // conic[0]
    float Bc = -s01 * inv;   // conic[1]
    float C  = s00 * inv;    // conic[2]

    sc_pA[rank] = 0.5f * A;
    sc_pB[rank] = Bc;
    sc_pC[rank] = 0.5f * C;

    // min eigenvalue of conic matrix [[A,B],[B,C]]  (PSD, so lmin>0)
    float half = 0.5f * (A - C);
    float lmin = 0.5f * (A + C) - sqrtf(half*half + Bc*Bc);
    lmin = fmaxf(lmin, 1e-8f);
    sc_rad[rank] = sqrtf(2.0f * CUT / lmin);

    sc_r[rank]  = sigmoidf_(feat[3*i + 0]);
    sc_g[rank]  = sigmoidf_(feat[3*i + 1]);
    sc_b[rank]  = sigmoidf_(feat[3*i + 2]);
    sc_al[rank] = sigmoidf_(opac[i]);
    d_ord[rank] = i;
}

// ---------------- kernel 2: Bezier-sampled means, written in sorted order ----
__global__ void prep_means(const float* __restrict__ ctrl)
{
    int g = blockIdx.x * 256 + threadIdx.x;    // 64 blocks x 256 = 16384
    int slot = g >> 6;                         // sorted curve slot
    int pt   = g & 63;
    int c    = d_ord[slot];                    // original curve
    int seg  = pt >> 5;                        // 0..1
    int s    = pt & 31;                        // 0..31

    float t = 0.007f + (float)s * (0.986f / 31.0f);
    float u = 1.0f - t;

    // Bernstein deg-5 weights: comb = {1,5,10,10,5,1}
    float t2 = t*t, t3 = t2*t, t4 = t3*t, t5 = t4*t;
    float u2 = u*u, u3 = u2*u, u4 = u3*u, u5 = u4*u;
    float w0 = u5;
    float w1 = 5.0f  * t  * u4;
    float w2 = 10.0f * t2 * u3;
    float w3 = 10.0f * t3 * u2;
    float w4 = 5.0f  * t4 * u;
    float w5 = t5;

    const float* cp = ctrl + c * N_CTRL * 2;
    // seg 0: ctrl 0..5 ; seg 1: ctrl 5,6,7,8,9,0  ((5+j)%10)
    int i0 = seg * 5;
    int i1 = i0 + 1, i2 = i0 + 2, i3 = i0 + 3, i4 = i0 + 4;
    int i5 = (i0 + 5) % N_CTRL;

    float px = w0*cp[2*i0+0] + w1*cp[2*i1+0] + w2*cp[2*i2+0]
             + w3*cp[2*i3+0] + w4*cp[2*i4+0] + w5*cp[2*i5+0];
    float py = w0*cp[2*i0+1] + w1*cp[2*i1+1] + w2*cp[2*i2+1]
             + w3*cp[2*i3+1] + w4*cp[2*i4+1] + w5*cp[2*i5+1];

    float mx = (tanhf(px) * 0.5f + 0.5f) * (float)IMG;
    float my = (tanhf(py) * 0.5f + 0.5f) * (float)IMG;
    g_mean[g] = make_float2(mx, my);
}

// ---------------- kernel 3: tiled alpha-compositing render -------------------
__global__ __launch_bounds__(256, 8)
void render(const float* __restrict__ bg, float* __restrict__ out)
{
    int tid  = threadIdx.x;
    int lx   = tid & 15;
    int ly   = tid >> 4;
    int lane = tid & 31;
    int wrp  = tid >> 5;

    float px = (float)(blockIdx.x * TILE + lx) + 0.5f;
    float py = (float)(blockIdx.y * TILE + ly) + 0.5f;
    float x0 = (float)(blockIdx.x * TILE) + 0.5f;
    float y0 = (float)(blockIdx.y * TILE) + 0.5f;
    float x1 = x0 + (float)(TILE - 1);
    float y1 = y0 + (float)(TILE - 1);

    __shared__ float smx[256], smy[256], sA[256], sB[256], sC[256];
    __shared__ float scr[256], scg[256], scb[256], sal[256];
    __shared__ int warpOff[8];
    __shared__ int s_cnt;

    float T = 1.0f, cr = 0.0f, cg = 0.0f, cb = 0.0f;

    for (int base = 0; base < NUM_GAUSS; base += 256) {
        int g = base + tid;
        float2 m = g_mean[g];
        int slot  = g >> 6;
        float rad = sc_rad[slot];

        bool keep = (m.x >= x0 - rad) && (m.x <= x1 + rad) &&
                    (m.y >= y0 - rad) && (m.y <= y1 + rad);

        unsigned mask = __ballot_sync(0xFFFFFFFFu, keep);
        if (lane == 0) warpOff[wrp] = __popc(mask);
        __syncthreads();
        if (tid == 0) {
            int acc = 0;
            #pragma unroll
            for (int k = 0; k < 8; k++) { int c = warpOff[k]; warpOff[k] = acc; acc += c; }
            s_cnt = acc;
        }
        __syncthreads();

        if (keep) {
            int pos = warpOff[wrp] + __popc(mask & ((1u << lane) - 1u));
            smx[pos] = m.x;        smy[pos] = m.y;
            sA [pos] = sc_pA[slot]; sB[pos] = sc_pB[slot]; sC[pos] = sc_pC[slot];
            scr[pos] = sc_r[slot];  scg[pos] = sc_g[slot]; scb[pos] = sc_b[slot];
            sal[pos] = sc_al[slot];
        }
        __syncthreads();

        int cnt = s_cnt;
        for (int j = 0; j < cnt; j++) {
            float dx = px - smx[j];
            float dy = py - smy[j];
            float p  = sA[j]*dx*dx + sB[j]*dx*dy + sC[j]*dy*dy;
            float a  = fminf(sal[j] * __expf(-p), 0.999f);
            float w  = a * T;
            cr += w * scr[j];
            cg += w * scg[j];
            cb += w * scb[j];
            T  -= w;               // T *= (1-a), exactly
        }

        // barrier doubles as "done writing smem" sync for next chunk
        if (__syncthreads_and(T < 1e-5f)) break;
    }

    float b0 = bg[0], b1 = bg[1], b2 = bg[2];
    int x = blockIdx.x * TILE + lx;
    int y = blockIdx.y * TILE + ly;
    int o = (y * IMG + x) * 3;
    out[o + 0] = fminf(fmaxf(cr + T * b0, 0.0f), 1.0f);
    out[o + 1] = fminf(fmaxf(cg + T * b1, 0.0f), 1.0f);
    out[o + 2] = fminf(fmaxf(cb + T * b2, 0.0f), 1.0f);
}

// ---------------- launch ----------------
extern "C" void kernel_launch(void* const* d_in, const int* in_sizes, int n_in,
                              void* d_out, int out_size)
{
    const float* ctrl  = (const float*)d_in[0];   // (256,10,2)
    const float* feat  = (const float*)d_in[1];   // (256,3)
    const float* chol  = (const float*)d_in[2];   // (256,3)
    const float* opac  = (const float*)d_in[3];   // (256,1)
    const float* depth = (const float*)d_in[4];   // (256,1)
    const float* bg    = (const float*)d_in[5];   // (3,)
    float* out = (float*)d_out;                   // (256,256,3)

    prep_curves<<<1, 256>>>(chol, feat, opac, depth);
    prep_means<<<64, 256>>>(ctrl);
    render<<<dim3(IMG / TILE, IMG / TILE), 256>>>(bg, out);
}

// round 2
// speedup vs baseline: 1.6770x; 1.6770x over previous
#include <cuda_runtime.h>
#include <math.h>

#define NUM_CURVES 256
#define N_CTRL 10
#define NUM_GAUSS 16384        // 256 curves * 64 points
#define IMG 256
#define TILE 16
#define NSEG 4                 // depth-range split per tile
#define GPS (NUM_GAUSS / NSEG) // gaussians per segment = 4096
#define CUT 12.0f

// ---------------- device globals (scratch) ----------------
__device__ float2 g_mean[NUM_GAUSS];            // depth-sorted centers
__device__ float4 g_con[NUM_CURVES];            // {0.5*A, B, 0.5*C, alpha} per sorted slot
__device__ float4 g_colrad[NUM_CURVES];         // {r, g, b, radius}     per sorted slot
__device__ float4 g_part[NSEG * IMG * IMG];     // per-segment partials {cr,cg,cb,T}

__device__ __forceinline__ float sigmoidf_(float x) {
    return 1.0f / (1.0f + __expf(-x));
}

// ---------------- kernel 1: fused prep (sort + params + means) ---------------
__global__ __launch_bounds__(256)
void prep(const float* __restrict__ ctrl,
          const float* __restrict__ feat,
          const float* __restrict__ chol,
          const float* __restrict__ opac,
          const float* __restrict__ depth)
{
    __shared__ float sd[NUM_CURVES];
    __shared__ int   sord[NUM_CURVES];   // rank -> original curve
    int i = threadIdx.x;

    sd[i] = depth[i];
    __syncthreads();

    float di = sd[i];
    int rank = 0;
    #pragma unroll 8
    for (int j = 0; j < NUM_CURVES; j++) {
        float dj = sd[j];
        rank += (dj < di) || (dj == di && j < i);   // stable argsort
    }
    sord[rank] = i;
    __syncthreads();

    if (blockIdx.x == 0) {
        // per-curve params, written at sorted slot `rank`
        float c0 = chol[3*i + 0] + 0.5f;
        float c1 = chol[3*i + 1];
        float c2 = chol[3*i + 2] + 0.5f;
        float s00 = c0*c0;
        float s01 = c0*c1;
        float s11 = c1*c1 + c2*c2;
        float inv = 1.0f / (s00*s11 - s01*s01);
        float A  = s11 * inv;
        float Bc = -s01 * inv;
        float C  = s00 * inv;

        // min eigenvalue of conic -> cutoff radius for exp(-CUT)
        float half = 0.5f * (A - C);
        float lmin = 0.5f * (A + C) - sqrtf(half*half + Bc*Bc);
        lmin = fmaxf(lmin, 1e-8f);
        float rad = sqrtf(2.0f * CUT / lmin);

        g_con[rank]    = make_float4(0.5f * A, Bc, 0.5f * C, sigmoidf_(opac[i]));
        g_colrad[rank] = make_float4(sigmoidf_(feat[3*i + 0]),
                                     sigmoidf_(feat[3*i + 1]),
                                     sigmoidf_(feat[3*i + 2]), rad);
    }

    // means for this block's 256 gaussians (sorted order)
    int g    = blockIdx.x * 256 + i;
    int slot = g >> 6;
    int pt   = g & 63;
    int c    = sord[slot];
    int seg  = pt >> 5;
    int s    = pt & 31;

    float t = 0.007f + (float)s * (0.986f / 31.0f);
    float u = 1.0f - t;
    float t2 = t*t, t3 = t2*t, t4 = t3*t, t5 = t4*t;
    float u2 = u*u, u3 = u2*u, u4 = u3*u, u5 = u4*u;
    float w0 = u5;
    float w1 = 5.0f  * t  * u4;
    float w2 = 10.0f * t2 * u3;
    float w3 = 10.0f * t3 * u2;
    float w4 = 5.0f  * t4 * u;
    float w5 = t5;

    const float* cp = ctrl + c * N_CTRL * 2;
    int i0 = seg * 5;
    int i5 = (i0 + 5) % N_CTRL;
    float px = w0*cp[2*i0+0] + w1*cp[2*(i0+1)+0] + w2*cp[2*(i0+2)+0]
             + w3*cp[2*(i0+3)+0] + w4*cp[2*(i0+4)+0] + w5*cp[2*i5+0];
    float py = w0*cp[2*i0+1] + w1*cp[2*(i0+1)+1] + w2*cp[2*(i0+2)+1]
             + w3*cp[2*(i0+3)+1] + w4*cp[2*(i0+4)+1] + w5*cp[2*i5+1];

    float mx = (tanhf(px) * 0.5f + 0.5f) * (float)IMG;
    float my = (tanhf(py) * 0.5f + 0.5f) * (float)IMG;
    g_mean[g] = make_float2(mx, my);
}

// ---------------- kernel 2: tiled render, depth-segmented --------------------
__global__ __launch_bounds__(256)
void render()
{
    int tid  = threadIdx.x;
    int lx   = tid & 15;
    int ly   = tid >> 4;
    int lane = tid & 31;
    int wrp  = tid >> 5;
    int seg  = blockIdx.z;

    float px = (float)(blockIdx.x * TILE + lx) + 0.5f;
    float py = (float)(blockIdx.y * TILE + ly) + 0.5f;
    float x0 = (float)(blockIdx.x * TILE) + 0.5f;
    float y0 = (float)(blockIdx.y * TILE) + 0.5f;
    float x1 = x0 + (float)(TILE - 1);
    float y1 = y0 + (float)(TILE - 1);

    __shared__ float4 sa[256];    // {mx, my, A, B}
    __shared__ float4 sb[256];    // {C, alpha, r, g}
    __shared__ float  sbl[256];   // b
    __shared__ int    wcnt[8];

    float T = 1.0f, cr = 0.0f, cg = 0.0f, cb = 0.0f;

    int gbase = seg * GPS;
    for (int chunk = 0; chunk < GPS / 256; chunk++) {
        int g    = gbase + chunk * 256 + tid;
        int slot = g >> 6;
        float2 m   = g_mean[g];
        float4 cr4 = g_colrad[slot];
        float  rad = cr4.w;

        bool keep = (m.x >= x0 - rad) && (m.x <= x1 + rad) &&
                    (m.y >= y0 - rad) && (m.y <= y1 + rad);

        unsigned mask = __ballot_sync(0xFFFFFFFFu, keep);
        if (lane == 0) wcnt[wrp] = __popc(mask);
        if (keep) {
            int pos = 32 * wrp + __popc(mask & ((1u << lane) - 1u));
            float4 con = g_con[slot];
            sa [pos] = make_float4(m.x, m.y, con.x, con.y);
            sb [pos] = make_float4(con.z, con.w, cr4.x, cr4.y);
            sbl[pos] = cr4.z;
        }
        __syncthreads();

        #pragma unroll
        for (int w = 0; w < 8; w++) {
            int cnt = wcnt[w];
            int jb  = 32 * w;
            for (int j = 0; j < cnt; j++) {
                float4 a4 = sa[jb + j];
                float4 b4 = sb[jb + j];
                float  bl = sbl[jb + j];
                float dx = px - a4.x;
                float dy = py - a4.y;
                float t1 = fmaf(a4.w, dy, a4.z * dx);
                float p  = fmaf(b4.x * dy, dy, t1 * dx);
                float e  = __expf(-p);
                float a  = fminf(b4.y * e, 0.999f);
                float w_ = a * T;
                cr = fmaf(w_, b4.z, cr);
                cg = fmaf(w_, b4.w, cg);
                cb = fmaf(w_, bl, cb);
                T -= w_;
            }
        }

        // barrier doubles as smem-reuse guard for next chunk
        if (__syncthreads_and(T < 1e-6f)) break;
    }

    int pix = (blockIdx.y * TILE + ly) * IMG + (blockIdx.x * TILE + lx);
    g_part[seg * (IMG * IMG) + pix] = make_float4(cr, cg, cb, T);
}

// ---------------- kernel 3: combine segments + background --------------------
__global__ __launch_bounds__(256)
void combine(const float* __restrict__ bg, float* __restrict__ out)
{
    int pix = blockIdx.x * 256 + threadIdx.x;

    float4 p0 = g_part[0 * (IMG * IMG) + pix];
    float4 p1 = g_part[1 * (IMG * IMG) + pix];
    float4 p2 = g_part[2 * (IMG * IMG) + pix];
    float4 p3 = g_part[3 * (IMG * IMG) + pix];

    float cr = p0.x, cg = p0.y, cb = p0.z, T = p0.w;
    cr = fmaf(T, p1.x, cr); cg = fmaf(T, p1.y, cg); cb = fmaf(T, p1.z, cb); T *= p1.w;
    cr = fmaf(T, p2.x, cr); cg = fmaf(T, p2.y, cg); cb = fmaf(T, p2.z, cb); T *= p2.w;
    cr = fmaf(T, p3.x, cr); cg = fmaf(T, p3.y, cg); cb = fmaf(T, p3.z, cb); T *= p3.w;

    float b0 = bg[0], b1 = bg[1], b2 = bg[2];
    int o = pix * 3;
    out[o + 0] = fminf(fmaxf(fmaf(T, b0, cr), 0.0f), 1.0f);
    out[o + 1] = fminf(fmaxf(fmaf(T, b1, cg), 0.0f), 1.0f);
    out[o + 2] = fminf(fmaxf(fmaf(T, b2, cb), 0.0f), 1.0f);
}

// ---------------- launch ----------------
extern "C" void kernel_launch(void* const* d_in, const int* in_sizes, int n_in,
                              void* d_out, int out_size)
{
    const float* ctrl  = (const float*)d_in[0];   // (256,10,2)
    const float* feat  = (const float*)d_in[1];   // (256,3)
    const float* chol  = (const float*)d_in[2];   // (256,3)
    const float* opac  = (const float*)d_in[3];   // (256,1)
    const float* depth = (const float*)d_in[4];   // (256,1)
    const float* bg    = (const float*)d_in[5];   // (3,)
    float* out = (float*)d_out;                   // (256,256,3)

    prep<<<64, 256>>>(ctrl, feat, chol, opac, depth);
    render<<<dim3(IMG / TILE, IMG / TILE, NSEG), 256>>>();
    combine<<<IMG * IMG / 256, 256>>>(bg, out);
}

// round 4
// speedup vs baseline: 2.6416x; 1.5752x over previous
#include <cuda_runtime.h>
#include <math.h>

#define NUM_CURVES 256
#define N_CTRL 10
#define NUM_GAUSS 16384        // 256 curves * 64 points
#define IMG 256
#define TILE 16
#define NTILE (IMG / TILE)     // 16
#define NSEG 4                 // depth-range split per tile
#define GPS (NUM_GAUSS / NSEG) // 4096 gaussians per segment
#define WPG (NUM_GAUSS / 32)   // 512 mask words per tile
#define WPS (GPS / 32)         // 128 mask words per (tile,seg)
#define CUT 12.0f

// ---------------- device globals (scratch) ----------------
__device__ float2   g_mean[NUM_GAUSS];              // depth-sorted centers
__device__ float4   g_con[NUM_CURVES];              // {0.5A, B, 0.5C, alpha} per sorted slot
__device__ float4   g_colrad[NUM_CURVES];           // {r, g, b, radius}
__device__ unsigned g_mask[NTILE * NTILE * WPG];    // per-tile survivor bitmask
__device__ float4   g_part[NSEG * IMG * IMG];       // per-segment partials {cr,cg,cb,T}

__device__ __forceinline__ float sigmoidf_(float x) { return 1.0f / (1.0f + __expf(-x)); }
__device__ __forceinline__ float ftanh_(float x)    { return 1.0f - 2.0f / (__expf(2.0f * x) + 1.0f); }

// ---------------- kernel 0: zero the bitmask ----------------
__global__ void zero_mask()
{
    int i = blockIdx.x * blockDim.x + threadIdx.x;     // 128*256 = 32768 threads
    uint4* p = reinterpret_cast<uint4*>(g_mask);       // 131072 words = 32768 uint4
    p[i] = make_uint4(0u, 0u, 0u, 0u);
}

// ---------------- kernel 1: sort + params + means + binning ----------------
__global__ __launch_bounds__(256)
void prep(const float* __restrict__ ctrl,
          const float* __restrict__ feat,
          const float* __restrict__ chol,
          const float* __restrict__ opac,
          const float* __restrict__ depth)
{
    __shared__ float sd[NUM_CURVES];
    __shared__ int   sord[NUM_CURVES];   // rank -> original curve
    int i = threadIdx.x;

    sd[i] = depth[i];
    __syncthreads();
    float di = sd[i];
    int rank = 0;
    #pragma unroll 16
    for (int j = 0; j < NUM_CURVES; j++) {
        float dj = sd[j];
        rank += (dj < di) || (dj == di && j < i);   // stable argsort
    }
    sord[rank] = i;
    __syncthreads();

    // this block's gaussian (sorted order)
    int g    = blockIdx.x * 256 + i;
    int slot = g >> 6;           // sorted curve slot 0..255
    int pt   = g & 63;
    int c    = sord[slot];       // original curve for this gaussian
    int seg  = pt >> 5;
    int s    = pt & 31;

    // per-curve conic/radius for curve c (recomputed redundantly; cheap)
    float c0 = chol[3*c + 0] + 0.5f;
    float c1 = chol[3*c + 1];
    float c2 = chol[3*c + 2] + 0.5f;
    float s00 = c0*c0, s01 = c0*c1, s11 = c1*c1 + c2*c2;
    float inv = 1.0f / (s00*s11 - s01*s01);
    float A = s11*inv, Bc = -s01*inv, C = s00*inv;
    float half = 0.5f * (A - C);
    float lmin = fmaxf(0.5f*(A + C) - sqrtf(half*half + Bc*Bc), 1e-8f);
    float rad  = sqrtf(2.0f * CUT / lmin);

    // exactly one writer per sorted slot: the pt==0 gaussian of that slot.
    // Values are for curve c == sord[slot] — consistent indexing.
    if (pt == 0) {
        g_con[slot]    = make_float4(0.5f*A, Bc, 0.5f*C, sigmoidf_(opac[c]));
        g_colrad[slot] = make_float4(sigmoidf_(feat[3*c+0]), sigmoidf_(feat[3*c+1]),
                                     sigmoidf_(feat[3*c+2]), rad);
    }

    // Bezier mean
    float t = 0.007f + (float)s * (0.986f / 31.0f);
    float u = 1.0f - t;
    float t2 = t*t, t3 = t2*t, t4 = t3*t, t5 = t4*t;
    float u2 = u*u, u3 = u2*u, u4 = u3*u, u5 = u4*u;
    float w0 = u5, w1 = 5.0f*t*u4, w2 = 10.0f*t2*u3,
          w3 = 10.0f*t3*u2, w4 = 5.0f*t4*u, w5 = t5;

    const float* cp = ctrl + c * N_CTRL * 2;
    int i0 = seg * 5;
    int i5 = (i0 + 5) % N_CTRL;
    float px = w0*cp[2*i0+0] + w1*cp[2*(i0+1)+0] + w2*cp[2*(i0+2)+0]
             + w3*cp[2*(i0+3)+0] + w4*cp[2*(i0+4)+0] + w5*cp[2*i5+0];
    float py = w0*cp[2*i0+1] + w1*cp[2*(i0+1)+1] + w2*cp[2*(i0+2)+1]
             + w3*cp[2*(i0+3)+1] + w4*cp[2*(i0+4)+1] + w5*cp[2*i5+1];

    float mx = (ftanh_(px) * 0.5f + 0.5f) * (float)IMG;
    float my = (ftanh_(py) * 0.5f + 0.5f) * (float)IMG;
    g_mean[g] = make_float2(mx, my);

    // binning: set bit g in every tile whose 16x16 pixel-center box overlaps disc
    int tx0 = max(0, (int)floorf((mx - rad - 0.5f) / (float)TILE));
    int tx1 = min(NTILE - 1, (int)floorf((mx + rad - 0.5f) / (float)TILE));
    int ty0 = max(0, (int)floorf((my - rad - 0.5f) / (float)TILE));
    int ty1 = min(NTILE - 1, (int)floorf((my + rad - 0.5f) / (float)TILE));
    unsigned bit  = 1u << (g & 31);
    int      word = g >> 5;
    for (int ty = ty0; ty <= ty1; ty++)
        for (int tx = tx0; tx <= tx1; tx++)
            atomicOr(&g_mask[(ty * NTILE + tx) * WPG + word], bit);
}

// ---------------- kernel 2: tiled render from survivor lists ----------------
__global__ __launch_bounds__(256)
void render()
{
    int tid  = threadIdx.x;
    int lx   = tid & 15;
    int ly   = tid >> 4;
    int lane = tid & 31;
    int wrp  = tid >> 5;
    int seg  = blockIdx.z;
    int tile = blockIdx.y * NTILE + blockIdx.x;

    float px = (float)(blockIdx.x * TILE + lx) + 0.5f;
    float py = (float)(blockIdx.y * TILE + ly) + 0.5f;

    __shared__ int    slist[GPS];     // survivor sorted-gaussian ids (depth order)
    __shared__ float4 sa[256];        // {mx, my, A, B}
    __shared__ float4 sb[256];        // {C, alpha, r, g}
    __shared__ float  sbl[256];       // b
    __shared__ int    s_wcnt[4];
    __shared__ int    s_cnt;

    // --- expand bitmask to index list (first 128 threads, order preserved) ---
    unsigned word = 0u;
    int cnt = 0;
    if (tid < WPS) {
        word = g_mask[tile * WPG + seg * WPS + tid];
        cnt  = __popc(word);
    }
    int scan = cnt;
    #pragma unroll
    for (int d = 1; d < 32; d <<= 1) {
        int v = __shfl_up_sync(0xFFFFFFFFu, scan, d);
        if (lane >= d) scan += v;
    }
    if (tid < WPS && lane == 31) s_wcnt[wrp] = scan;
    __syncthreads();
    if (tid == 0) s_cnt = s_wcnt[0] + s_wcnt[1] + s_wcnt[2] + s_wcnt[3];
    if (tid < WPS) {
        int off = scan - cnt;                       // exclusive prefix within warp
        #pragma unroll
        for (int k = 0; k < 4; k++) if (k < wrp) off += s_wcnt[k];
        int gb = seg * GPS + tid * 32;
        while (word) {
            int b = __ffs(word) - 1;
            word &= word - 1;
            slist[off++] = gb + b;
        }
    }
    __syncthreads();

    int total = s_cnt;
    float T = 1.0f, cr = 0.0f, cg = 0.0f, cb = 0.0f;

    for (int base = 0; base < total; base += 256) {
        int n = min(256, total - base);
        if (tid < n) {
            int g    = slist[base + tid];
            int slot = g >> 6;
            float2 m   = g_mean[g];
            float4 con = g_con[slot];
            float4 cl  = g_colrad[slot];
            sa [tid] = make_float4(m.x, m.y, con.x, con.y);
            sb [tid] = make_float4(con.z, con.w, cl.x, cl.y);
            sbl[tid] = cl.z;
        }
        __syncthreads();

        for (int j = 0; j < n; j++) {
            float4 a4 = sa[j];
            float4 b4 = sb[j];
            float  bl = sbl[j];
            float dx = px - a4.x;
            float dy = py - a4.y;
            float t1 = fmaf(a4.w, dy, a4.z * dx);
            float p  = fmaf(b4.x * dy, dy, t1 * dx);
            float a  = fminf(b4.y * __expf(-p), 0.999f);
            float w_ = a * T;
            cr = fmaf(w_, b4.z, cr);
            cg = fmaf(w_, b4.w, cg);
            cb = fmaf(w_, bl, cb);
            T -= w_;
        }

        if (__syncthreads_and(T < 1e-6f)) break;   // also guards smem reuse
    }

    int pix = (blockIdx.y * TILE + ly) * IMG + (blockIdx.x * TILE + lx);
    g_part[seg * (IMG * IMG) + pix] = make_float4(cr, cg, cb, T);
}

// ---------------- kernel 3: combine segments + background ----------------
__global__ __launch_bounds__(256)
void combine(const float* __restrict__ bg, float* __restrict__ out)
{
    int pix = blockIdx.x * 256 + threadIdx.x;

    float4 p0 = g_part[0 * (IMG*IMG) + pix];
    float4 p1 = g_part[1 * (IMG*IMG) + pix];
    float4 p2 = g_part[2 * (IMG*IMG) + pix];
    float4 p3 = g_part[3 * (IMG*IMG) + pix];

    float cr = p0.x, cg = p0.y, cb = p0.z, T = p0.w;
    cr = fmaf(T, p1.x, cr); cg = fmaf(T, p1.y, cg); cb = fmaf(T, p1.z, cb); T *= p1.w;
    cr = fmaf(T, p2.x, cr); cg = fmaf(T, p2.y, cg); cb = fmaf(T, p2.z, cb); T *= p2.w;
    cr = fmaf(T, p3.x, cr); cg = fmaf(T, p3.y, cg); cb = fmaf(T, p3.z, cb); T *= p3.w;

    float b0 = bg[0], b1 = bg[1], b2 = bg[2];
    int o = pix * 3;
    out[o + 0] = fminf(fmaxf(fmaf(T, b0, cr), 0.0f), 1.0f);
    out[o + 1] = fminf(fmaxf(fmaf(T, b1, cg), 0.0f), 1.0f);
    out[o + 2] = fminf(fmaxf(fmaf(T, b2, cb), 0.0f), 1.0f);
}

// ---------------- launch ----------------
extern "C" void kernel_launch(void* const* d_in, const int* in_sizes, int n_in,
                              void* d_out, int out_size)
{
    const float* ctrl  = (const float*)d_in[0];   // (256,10,2)
    const float* feat  = (const float*)d_in[1];   // (256,3)
    const float* chol  = (const float*)d_in[2];   // (256,3)
    const float* opac  = (const float*)d_in[3];   // (256,1)
    const float* depth = (const float*)d_in[4];   // (256,1)
    const float* bg    = (const float*)d_in[5];   // (3,)
    float* out = (float*)d_out;                   // (256,256,3)

    zero_mask<<<128, 256>>>();
    prep<<<64, 256>>>(ctrl, feat, chol, opac, depth);
    render<<<dim3(NTILE, NTILE, NSEG), 256>>>();
    combine<<<IMG * IMG / 256, 256>>>(bg, out);
}

// round 5
// speedup vs baseline: 2.6711x; 1.0112x over previous
#include <cuda_runtime.h>
#include <math.h>

#define NUM_CURVES 256
#define N_CTRL 10
#define NUM_GAUSS 16384        // 256 curves * 64 points
#define IMG 256
#define TILE 16
#define NTILE (IMG / TILE)     // 16
#define NSEG 4                 // depth-range split per tile
#define GPS (NUM_GAUSS / NSEG) // 4096 gaussians per segment
#define WPG (NUM_GAUSS / 32)   // 512 mask words per tile
#define WPS (GPS / 32)         // 128 mask words per (tile,seg)
#define CUT 10.0f

// ---------------- device globals (scratch; zero-initialized at load) --------
__device__ float2   g_mean[NUM_GAUSS];              // depth-sorted centers
__device__ float4   g_con[NUM_CURVES];              // {0.5A, B, 0.5C, alpha} per sorted slot
__device__ float4   g_colrad[NUM_CURVES];           // {r, g, b, radius}
__device__ unsigned g_mask[NTILE * NTILE * WPG];    // per-tile survivor bitmask (idempotent OR)
__device__ float4   g_part[NSEG * IMG * IMG];       // per-segment partials {cr,cg,cb,T}
__device__ int      g_cnt[NTILE * NTILE];           // per-tile done counters (self-resetting)

__device__ __forceinline__ float sigmoidf_(float x) { return 1.0f / (1.0f + __expf(-x)); }
__device__ __forceinline__ float ftanh_(float x)    { return 1.0f - 2.0f / (__expf(2.0f * x) + 1.0f); }

// ---------------- kernel 1: sort + params + means + binning ----------------
__global__ __launch_bounds__(256)
void prep(const float* __restrict__ ctrl,
          const float* __restrict__ feat,
          const float* __restrict__ chol,
          const float* __restrict__ opac,
          const float* __restrict__ depth)
{
    __shared__ float sd[NUM_CURVES];
    __shared__ int   sord[NUM_CURVES];   // rank -> original curve
    int i = threadIdx.x;

    sd[i] = depth[i];
    __syncthreads();
    float di = sd[i];
    int rank = 0;
    #pragma unroll 16
    for (int j = 0; j < NUM_CURVES; j++) {
        float dj = sd[j];
        rank += (dj < di) || (dj == di && j < i);   // stable argsort
    }
    sord[rank] = i;
    __syncthreads();

    // this block's gaussian (sorted order)
    int g    = blockIdx.x * 256 + i;
    int slot = g >> 6;           // sorted curve slot 0..255
    int pt   = g & 63;
    int c    = sord[slot];       // original curve for this gaussian
    int seg  = pt >> 5;
    int s    = pt & 31;

    // per-curve conic/radius for curve c
    float c0 = chol[3*c + 0] + 0.5f;
    float c1 = chol[3*c + 1];
    float c2 = chol[3*c + 2] + 0.5f;
    float s00 = c0*c0, s01 = c0*c1, s11 = c1*c1 + c2*c2;
    float inv = 1.0f / (s00*s11 - s01*s01);
    float A = s11*inv, Bc = -s01*inv, C = s00*inv;
    float half = 0.5f * (A - C);
    float lmin = fmaxf(0.5f*(A + C) - sqrtf(half*half + Bc*Bc), 1e-8f);
    float rad  = sqrtf(2.0f * CUT / lmin);

    // exactly one writer per sorted slot (pt==0), values for curve c == sord[slot]
    if (pt == 0) {
        g_con[slot]    = make_float4(0.5f*A, Bc, 0.5f*C, sigmoidf_(opac[c]));
        g_colrad[slot] = make_float4(sigmoidf_(feat[3*c+0]), sigmoidf_(feat[3*c+1]),
                                     sigmoidf_(feat[3*c+2]), rad);
    }

    // Bezier mean
    float t = 0.007f + (float)s * (0.986f / 31.0f);
    float u = 1.0f - t;
    float t2 = t*t, t3 = t2*t, t4 = t3*t, t5 = t4*t;
    float u2 = u*u, u3 = u2*u, u4 = u3*u, u5 = u4*u;
    float w0 = u5, w1 = 5.0f*t*u4, w2 = 10.0f*t2*u3,
          w3 = 10.0f*t3*u2, w4 = 5.0f*t4*u, w5 = t5;

    const float* cp = ctrl + c * N_CTRL * 2;
    int i0 = seg * 5;
    int i5 = (i0 + 5) % N_CTRL;
    float px = w0*cp[2*i0+0] + w1*cp[2*(i0+1)+0] + w2*cp[2*(i0+2)+0]
             + w3*cp[2*(i0+3)+0] + w4*cp[2*(i0+4)+0] + w5*cp[2*i5+0];
    float py = w0*cp[2*i0+1] + w1*cp[2*(i0+1)+1] + w2*cp[2*(i0+2)+1]
             + w3*cp[2*(i0+3)+1] + w4*cp[2*(i0+4)+1] + w5*cp[2*i5+1];

    float mx = (ftanh_(px) * 0.5f + 0.5f) * (float)IMG;
    float my = (ftanh_(py) * 0.5f + 0.5f) * (float)IMG;
    g_mean[g] = make_float2(mx, my);

    // binning: set bit g in every tile whose 16x16 pixel-center box overlaps disc
    int tx0 = max(0, (int)floorf((mx - rad - 0.5f) / (float)TILE));
    int tx1 = min(NTILE - 1, (int)floorf((mx + rad - 0.5f) / (float)TILE));
    int ty0 = max(0, (int)floorf((my - rad - 0.5f) / (float)TILE));
    int ty1 = min(NTILE - 1, (int)floorf((my + rad - 0.5f) / (float)TILE));
    unsigned bit  = 1u << (g & 31);
    int      word = g >> 5;
    for (int ty = ty0; ty <= ty1; ty++)
        for (int tx = tx0; tx <= tx1; tx++)
            atomicOr(&g_mask[(ty * NTILE + tx) * WPG + word], bit);
}

// ---------------- kernel 2: tiled render + fused per-tile combine -----------
__global__ __launch_bounds__(256)
void render(const float* __restrict__ bg, float* __restrict__ out)
{
    int tid  = threadIdx.x;
    int lx   = tid & 15;
    int ly   = tid >> 4;
    int lane = tid & 31;
    int wrp  = tid >> 5;
    int seg  = blockIdx.z;
    int tile = blockIdx.y * NTILE + blockIdx.x;

    float px = (float)(blockIdx.x * TILE + lx) + 0.5f;
    float py = (float)(blockIdx.y * TILE + ly) + 0.5f;

    __shared__ int    slist[GPS];     // survivor sorted-gaussian ids (depth order)
    __shared__ float4 sa[256];        // {mx, my, A, B}
    __shared__ float4 sb[256];        // {C, alpha, r, g}
    __shared__ float  sbl[256];       // b
    __shared__ int    s_wcnt[4];
    __shared__ int    s_cnt;
    __shared__ int    s_old;

    // --- expand bitmask to index list (first 128 threads, order preserved) ---
    unsigned word = 0u;
    int cnt = 0;
    if (tid < WPS) {
        word = g_mask[tile * WPG + seg * WPS + tid];
        cnt  = __popc(word);
    }
    int scan = cnt;
    #pragma unroll
    for (int d = 1; d < 32; d <<= 1) {
        int v = __shfl_up_sync(0xFFFFFFFFu, scan, d);
        if (lane >= d) scan += v;
    }
    if (tid < WPS && lane == 31) s_wcnt[wrp] = scan;
    __syncthreads();
    if (tid == 0) s_cnt = s_wcnt[0] + s_wcnt[1] + s_wcnt[2] + s_wcnt[3];
    if (tid < WPS) {
        int off = scan - cnt;                       // exclusive prefix within warp
        #pragma unroll
        for (int k = 0; k < 4; k++) if (k < wrp) off += s_wcnt[k];
        int gb = seg * GPS + tid * 32;
        while (word) {
            int b = __ffs(word) - 1;
            word &= word - 1;
            slist[off++] = gb + b;
        }
    }
    __syncthreads();

    int total = s_cnt;
    float T = 1.0f, cr = 0.0f, cg = 0.0f, cb = 0.0f;

    for (int base = 0; base < total; base += 256) {
        int n = min(256, total - base);
        if (tid < n) {
            int g    = slist[base + tid];
            int slot = g >> 6;
            float2 m   = g_mean[g];
            float4 con = g_con[slot];
            float4 cl  = g_colrad[slot];
            sa [tid] = make_float4(m.x, m.y, con.x, con.y);
            sb [tid] = make_float4(con.z, con.w, cl.x, cl.y);
            sbl[tid] = cl.z;
        }
        __syncthreads();

        for (int j = 0; j < n; j++) {
            float4 a4 = sa[j];
            float4 b4 = sb[j];
            float  bl = sbl[j];
            float dx = px - a4.x;
            float dy = py - a4.y;
            float t1 = fmaf(a4.w, dy, a4.z * dx);
            float p  = fmaf(b4.x * dy, dy, t1 * dx);
            float a  = fminf(b4.y * __expf(-p), 0.999f);
            float w_ = a * T;
            cr = fmaf(w_, b4.z, cr);
            cg = fmaf(w_, b4.w, cg);
            cb = fmaf(w_, bl, cb);
            T -= w_;
        }

        if (__syncthreads_and(T < 1e-6f)) break;   // also guards smem reuse
    }

    int pix = (blockIdx.y * TILE + ly) * IMG + (blockIdx.x * TILE + lx);
    g_part[seg * (IMG * IMG) + pix] = make_float4(cr, cg, cb, T);

    // ---- last-block-done combine (replaces separate combine kernel) ----
    __threadfence();
    __syncthreads();
    if (tid == 0) s_old = atomicAdd(&g_cnt[tile], 1);
    __syncthreads();

    if (s_old == 3) {
        __threadfence();   // acquire: order partial reads after counter read
        float4 p0 = g_part[0 * (IMG*IMG) + pix];
        float4 p1 = g_part[1 * (IMG*IMG) + pix];
        float4 p2 = g_part[2 * (IMG*IMG) + pix];
        float4 p3 = g_part[3 * (IMG*IMG) + pix];

        float fr = p0.x, fg = p0.y, fb = p0.z, fT = p0.w;
        fr = fmaf(fT, p1.x, fr); fg = fmaf(fT, p1.y, fg); fb = fmaf(fT, p1.z, fb); fT *= p1.w;
        fr = fmaf(fT, p2.x, fr); fg = fmaf(fT, p2.y, fg); fb = fmaf(fT, p2.z, fb); fT *= p2.w;
        fr = fmaf(fT, p3.x, fr); fg = fmaf(fT, p3.y, fg); fb = fmaf(fT, p3.z, fb); fT *= p3.w;

        float b0 = bg[0], b1 = bg[1], b2 = bg[2];
        int o = pix * 3;
        out[o + 0] = fminf(fmaxf(fmaf(fT, b0, fr), 0.0f), 1.0f);
        out[o + 1] = fminf(fmaxf(fmaf(fT, b1, fg), 0.0f), 1.0f);
        out[o + 2] = fminf(fmaxf(fmaf(fT, b2, fb), 0.0f), 1.0f);

        if (tid == 0) g_cnt[tile] = 0;   // self-reset for next graph replay
    }
}

// ---------------- launch ----------------
extern "C" void kernel_launch(void* const* d_in, const int* in_sizes, int n_in,
                              void* d_out, int out_size)
{
    const float* ctrl  = (const float*)d_in[0];   // (256,10,2)
    const float* feat  = (const float*)d_in[1];   // (256,3)
    const float* chol  = (const float*)d_in[2];   // (256,3)
    const float* opac  = (const float*)d_in[3];   // (256,1)
    const float* depth = (const float*)d_in[4];   // (256,1)
    const float* bg    = (const float*)d_in[5];   // (3,)
    float* out = (float*)d_out;                   // (256,256,3)

    prep<<<64, 256>>>(ctrl, feat, chol, opac, depth);
    render<<<dim3(NTILE, NTILE, NSEG), 256>>>(bg, out);
}

// round 6
// speedup vs baseline: 3.5964x; 1.3464x over previous
#include <cuda_runtime.h>
#include <math.h>

#define NUM_CURVES 256
#define N_CTRL 10
#define NUM_GAUSS 16384        // 256 curves * 64 points
#define IMG 256
#define TILE 16
#define NTILE (IMG / TILE)     // 16
#define NSEG 4                 // depth-range split per tile
#define GPS (NUM_GAUSS / NSEG) // 4096 gaussians per segment
#define WPG (NUM_GAUSS / 32)   // 512 mask words per tile
#define WPS (GPS / 32)         // 128 mask words per (tile,seg)
#define CUT 8.0f
#define LOG2E 1.4426950408889634f

// ---------------- device globals (scratch; zero-initialized at load) --------
__device__ float2   g_mean[NUM_GAUSS];              // depth-sorted centers
__device__ float4   g_con[NUM_CURVES];              // {A2, B2, C2, log2(alpha)}  (exp2-scaled conic)
__device__ float4   g_col[NUM_CURVES];              // {r, g, b, ry}
__device__ unsigned g_mask[NTILE * NTILE * WPG];    // per-tile survivor bitmask (idempotent OR)
__device__ float4   g_part[NSEG * IMG * IMG];       // per-segment partials {cr,cg,cb,T}
__device__ int      g_cnt[NTILE * NTILE];           // per-tile done counters (self-resetting)

__device__ __forceinline__ float sigmoidf_(float x) { return 1.0f / (1.0f + __expf(-x)); }
__device__ __forceinline__ float ftanh_(float x)    { return 1.0f - 2.0f / (__expf(2.0f * x) + 1.0f); }

// ---------------- kernel 1: sort + params + means + binning ----------------
__global__ __launch_bounds__(256)
void prep(const float* __restrict__ ctrl,
          const float* __restrict__ feat,
          const float* __restrict__ chol,
          const float* __restrict__ opac,
          const float* __restrict__ depth)
{
    __shared__ float sd[NUM_CURVES];
    __shared__ int   sord[NUM_CURVES];   // rank -> original curve
    int i = threadIdx.x;

    sd[i] = depth[i];
    __syncthreads();
    float di = sd[i];
    int rank = 0;
    #pragma unroll 16
    for (int j = 0; j < NUM_CURVES; j++) {
        float dj = sd[j];
        rank += (dj < di) || (dj == di && j < i);   // stable argsort
    }
    sord[rank] = i;
    __syncthreads();

    // this block's gaussian (sorted order)
    int g    = blockIdx.x * 256 + i;
    int slot = g >> 6;           // sorted curve slot
    int pt   = g & 63;
    int c    = sord[slot];       // original curve
    int seg  = pt >> 5;
    int s    = pt & 31;

    // covariance / conic for curve c
    float c0 = chol[3*c + 0] + 0.5f;
    float c1 = chol[3*c + 1];
    float c2 = chol[3*c + 2] + 0.5f;
    float s00 = c0*c0, s01 = c0*c1, s11 = c1*c1 + c2*c2;   // covariance
    float inv = 1.0f / (s00*s11 - s01*s01);
    float A = s11*inv, Bc = -s01*inv, C = s00*inv;          // conic
    // exact per-axis extents of {0.5 A dx^2 + B dx dy + 0.5 C dy^2 <= CUT}:
    float rx = sqrtf(2.0f * CUT * s00);
    float ry = sqrtf(2.0f * CUT * s11);

    // one writer per sorted slot (pt==0); values for curve c == sord[slot]
    if (pt == 0) {
        float al = sigmoidf_(opac[c]);
        g_con[slot] = make_float4(0.5f*A*LOG2E, Bc*LOG2E, 0.5f*C*LOG2E, log2f(al));
        g_col[slot] = make_float4(sigmoidf_(feat[3*c+0]), sigmoidf_(feat[3*c+1]),
                                  sigmoidf_(feat[3*c+2]), ry);
    }

    // Bezier mean
    float t = 0.007f + (float)s * (0.986f / 31.0f);
    float u = 1.0f - t;
    float t2 = t*t, t3 = t2*t, t4 = t3*t, t5 = t4*t;
    float u2 = u*u, u3 = u2*u, u4 = u3*u, u5 = u4*u;
    float w0 = u5, w1 = 5.0f*t*u4, w2 = 10.0f*t2*u3,
          w3 = 10.0f*t3*u2, w4 = 5.0f*t4*u, w5 = t5;

    const float* cp = ctrl + c * N_CTRL * 2;
    int i0 = seg * 5;
    int i5 = (i0 + 5) % N_CTRL;
    float px = w0*cp[2*i0+0] + w1*cp[2*(i0+1)+0] + w2*cp[2*(i0+2)+0]
             + w3*cp[2*(i0+3)+0] + w4*cp[2*(i0+4)+0] + w5*cp[2*i5+0];
    float py = w0*cp[2*i0+1] + w1*cp[2*(i0+1)+1] + w2*cp[2*(i0+2)+1]
             + w3*cp[2*(i0+3)+1] + w4*cp[2*(i0+4)+1] + w5*cp[2*i5+1];

    float mx = (ftanh_(px) * 0.5f + 0.5f) * (float)IMG;
    float my = (ftanh_(py) * 0.5f + 0.5f) * (float)IMG;
    g_mean[g] = make_float2(mx, my);

    // binning with per-axis extents (tighter than circumscribed circle)
    int tx0 = max(0, (int)floorf((mx - rx - 0.5f) / (float)TILE));
    int tx1 = min(NTILE - 1, (int)floorf((mx + rx - 0.5f) / (float)TILE));
    int ty0 = max(0, (int)floorf((my - ry - 0.5f) / (float)TILE));
    int ty1 = min(NTILE - 1, (int)floorf((my + ry - 0.5f) / (float)TILE));
    unsigned bit  = 1u << (g & 31);
    int      word = g >> 5;
    for (int ty = ty0; ty <= ty1; ty++)
        for (int tx = tx0; tx <= tx1; tx++)
            atomicOr(&g_mask[(ty * NTILE + tx) * WPG + word], bit);
}

// ---------------- kernel 2: tiled render (2 px/thread) + fused combine ------
__global__ __launch_bounds__(128)
void render(const float* __restrict__ bg, float* __restrict__ out)
{
    int tid  = threadIdx.x;               // 128 threads
    int lx   = tid & 15;
    int gy   = tid >> 4;                  // 0..7 (row-pair index)
    int lane = tid & 31;
    int wrp  = tid >> 5;                  // 4 warps; warp w covers rows 4w..4w+3
    int seg  = blockIdx.z;
    int tile = blockIdx.y * NTILE + blockIdx.x;

    float X0  = (float)(blockIdx.x * TILE);
    float Y0  = (float)(blockIdx.y * TILE);
    float px  = X0 + (float)lx + 0.5f;
    float py0 = Y0 + (float)(2*gy)     + 0.5f;
    float py1 = py0 + 1.0f;
    float wcy = Y0 + (float)(4*wrp) + 2.0f;   // warp's y center; halfspan 1.5

    __shared__ int    slist[GPS];     // survivor ids (depth order)
    __shared__ float4 sa[128];        // {mx, my, ry, l2alpha}
    __shared__ float4 sb[128];        // {A2, B2, C2, r}
    __shared__ float2 sc[128];        // {g, b}
    __shared__ int    s_wcnt[4];
    __shared__ int    s_cnt;
    __shared__ int    s_old;

    // --- expand bitmask to index list (128 threads, order preserved) ---
    unsigned word = g_mask[tile * WPG + seg * WPS + tid];
    int cnt = __popc(word);
    int scan = cnt;
    #pragma unroll
    for (int d = 1; d < 32; d <<= 1) {
        int v = __shfl_up_sync(0xFFFFFFFFu, scan, d);
        if (lane >= d) scan += v;
    }
    if (lane == 31) s_wcnt[wrp] = scan;
    __syncthreads();
    if (tid == 0) s_cnt = s_wcnt[0] + s_wcnt[1] + s_wcnt[2] + s_wcnt[3];
    {
        int off = scan - cnt;
        #pragma unroll
        for (int k = 0; k < 4; k++) if (k < wrp) off += s_wcnt[k];
        int gb = seg * GPS + tid * 32;
        while (word) {
            int b = __ffs(word) - 1;
            word &= word - 1;
            slist[off++] = gb + b;
        }
    }
    __syncthreads();

    int total = s_cnt;
    float T0 = 1.0f, cr0 = 0.0f, cg0 = 0.0f, cb0 = 0.0f;
    float T1 = 1.0f, cr1 = 0.0f, cg1 = 0.0f, cb1 = 0.0f;

    for (int base = 0; base < total; base += 128) {
        int n = min(128, total - base);
        if (tid < n) {
            int g    = slist[base + tid];
            int slot = g >> 6;
            float2 m   = g_mean[g];
            float4 con = g_con[slot];      // A2,B2,C2,l2a
            float4 cl  = g_col[slot];      // r,g,b,ry
            sa[tid] = make_float4(m.x, m.y, cl.w, con.w);
            sb[tid] = make_float4(con.x, con.y, con.z, cl.x);
            sc[tid] = make_float2(cl.y, cl.z);
        }
        __syncthreads();

        for (int j = 0; j < n; j++) {
            float4 a4 = sa[j];                       // mx,my,ry,l2a
            // warp-strip cull: all 4 rows of this warp outside the y-extent
            if (fabsf(a4.y - wcy) > a4.z + 1.5f) continue;
            float4 b4 = sb[j];                       // A2,B2,C2,r
            float2 c2 = sc[j];                       // g,b
            float dx  = px  - a4.x;
            float dy0 = py0 - a4.y;
            float dy1 = py1 - a4.y;
            float ax  = b4.x * dx;                   // shared across both pixels
            float p0  = fmaf(fmaf(b4.y, dy0, ax), dx, (b4.z * dy0) * dy0);
            float p1  = fmaf(fmaf(b4.y, dy1, ax), dx, (b4.z * dy1) * dy1);
            float a0  = fminf(exp2f(a4.w - p0), 0.999f);
            float a1  = fminf(exp2f(a4.w - p1), 0.999f);
            float w0_ = a0 * T0;
            float w1_ = a1 * T1;
            cr0 = fmaf(w0_, b4.w, cr0); cg0 = fmaf(w0_, c2.x, cg0); cb0 = fmaf(w0_, c2.y, cb0);
            cr1 = fmaf(w1_, b4.w, cr1); cg1 = fmaf(w1_, c2.x, cg1); cb1 = fmaf(w1_, c2.y, cb1);
            T0 -= w0_;
            T1 -= w1_;
        }

        if (__syncthreads_and((T0 < 1e-6f) & (T1 < 1e-6f))) break;   // guards smem reuse too
    }

    int pix0 = (blockIdx.y * TILE + 2*gy) * IMG + (blockIdx.x * TILE + lx);
    int pix1 = pix0 + IMG;
    g_part[seg * (IMG*IMG) + pix0] = make_float4(cr0, cg0, cb0, T0);
    g_part[seg * (IMG*IMG) + pix1] = make_float4(cr1, cg1, cb1, T1);

    // ---- last-block-done combine ----
    __threadfence();
    __syncthreads();
    if (tid == 0) s_old = atomicAdd(&g_cnt[tile], 1);
    __syncthreads();

    if (s_old == 3) {
        __threadfence();
        float b0 = bg[0], b1 = bg[1], b2 = bg[2];
        #pragma unroll
        for (int k = 0; k < 2; k++) {
            int pix = k ? pix1 : pix0;
            float4 p0 = g_part[0 * (IMG*IMG) + pix];
            float4 p1 = g_part[1 * (IMG*IMG) + pix];
            float4 p2 = g_part[2 * (IMG*IMG) + pix];
            float4 p3 = g_part[3 * (IMG*IMG) + pix];

            float fr = p0.x, fg = p0.y, fb = p0.z, fT = p0.w;
            fr = fmaf(fT, p1.x, fr); fg = fmaf(fT, p1.y, fg); fb = fmaf(fT, p1.z, fb); fT *= p1.w;
            fr = fmaf(fT, p2.x, fr); fg = fmaf(fT, p2.y, fg); fb = fmaf(fT, p2.z, fb); fT *= p2.w;
            fr = fmaf(fT, p3.x, fr); fg = fmaf(fT, p3.y, fg); fb = fmaf(fT, p3.z, fb); fT *= p3.w;

            int o = pix * 3;
            out[o + 0] = fminf(fmaxf(fmaf(fT, b0, fr), 0.0f), 1.0f);
            out[o + 1] = fminf(fmaxf(fmaf(fT, b1, fg), 0.0f), 1.0f);
            out[o + 2] = fminf(fmaxf(fmaf(fT, b2, fb), 0.0f), 1.0f);
        }
        if (tid == 0) g_cnt[tile] = 0;   // self-reset for next replay
    }
}

// ---------------- launch ----------------
extern "C" void kernel_launch(void* const* d_in, const int* in_sizes, int n_in,
                              void* d_out, int out_size)
{
    const float* ctrl  = (const float*)d_in[0];   // (256,10,2)
    const float* feat  = (const float*)d_in[1];   // (256,3)
    const float* chol  = (const float*)d_in[2];   // (256,3)
    const float* opac  = (const float*)d_in[3];   // (256,1)
    const float* depth = (const float*)d_in[4];   // (256,1)
    const float* bg    = (const float*)d_in[5];   // (3,)
    float* out = (float*)d_out;                   // (256,256,3)

    prep<<<64, 256>>>(ctrl, feat, chol, opac, depth);
    render<<<dim3(NTILE, NTILE, NSEG), 128>>>(bg, out);
}